// round 1
// baseline (speedup 1.0000x reference)
#include <cuda_runtime.h>
#include <math_constants.h>

// Jagged log-softmax:
//   in:  logits (float32, TOTAL=16777216), prefix_sum (int32, SEGS=8192)
//   segment j = [prefix_sum[j-1], prefix_sum[j])  (prefix_sum[-1] := 0)
//   out[i] = logits[i] - (seg_max + log(seg_sumexp))
//
// One block per segment; 3 passes (max, sumexp, write). Passes 2-3 hit
// L1/L2 since avg segment = 8KB, max ~74KB.

#define THREADS 256
#define NWARPS (THREADS / 32)

__device__ __forceinline__ float warp_reduce_max(float v) {
    #pragma unroll
    for (int o = 16; o > 0; o >>= 1)
        v = fmaxf(v, __shfl_xor_sync(0xFFFFFFFFu, v, o));
    return v;
}
__device__ __forceinline__ float warp_reduce_sum(float v) {
    #pragma unroll
    for (int o = 16; o > 0; o >>= 1)
        v += __shfl_xor_sync(0xFFFFFFFFu, v, o);
    return v;
}

__global__ void __launch_bounds__(THREADS)
jagged_log_softmax_kernel(const float* __restrict__ logits,
                          const int* __restrict__ prefix_sum,
                          float* __restrict__ out) {
    __shared__ float smem[NWARPS];
    __shared__ float s_bcast;

    const int seg   = blockIdx.x;
    const int start = (seg == 0) ? 0 : prefix_sum[seg - 1];
    const int end   = prefix_sum[seg];
    if (start >= end) return;

    const int tid  = threadIdx.x;
    const int lane = tid & 31;
    const int warp = tid >> 5;

    // ---- Pass 1: segment max ----
    float m = -CUDART_INF_F;
    for (int i = start + tid; i < end; i += THREADS)
        m = fmaxf(m, __ldg(&logits[i]));
    m = warp_reduce_max(m);
    if (lane == 0) smem[warp] = m;
    __syncthreads();
    if (warp == 0) {
        float v = (lane < NWARPS) ? smem[lane] : -CUDART_INF_F;
        v = warp_reduce_max(v);
        if (lane == 0) s_bcast = v;
    }
    __syncthreads();
    const float seg_max = s_bcast;
    __syncthreads();

    // ---- Pass 2: sum of exp(x - max) ----
    float s = 0.0f;
    for (int i = start + tid; i < end; i += THREADS)
        s += __expf(__ldg(&logits[i]) - seg_max);
    s = warp_reduce_sum(s);
    if (lane == 0) smem[warp] = s;
    __syncthreads();
    if (warp == 0) {
        float v = (lane < NWARPS) ? smem[lane] : 0.0f;
        v = warp_reduce_sum(v);
        if (lane == 0) s_bcast = v;
    }
    __syncthreads();
    const float lse = seg_max + __logf(s_bcast);

    // ---- Pass 3: write ----
    for (int i = start + tid; i < end; i += THREADS)
        out[i] = __ldg(&logits[i]) - lse;
}

extern "C" void kernel_launch(void* const* d_in, const int* in_sizes, int n_in,
                              void* d_out, int out_size) {
    const float* logits     = (const float*)d_in[0];
    const int*   prefix_sum = (const int*)d_in[1];
    float*       out        = (float*)d_out;

    const int num_segs = in_sizes[1];
    jagged_log_softmax_kernel<<<num_segs, THREADS>>>(logits, prefix_sum, out);
}